// round 14
// baseline (speedup 1.0000x reference)
#include <cuda_runtime.h>
#include <cstdint>

#define NN    2000
#define D     16
#define TILE  8192           // B*T*D = 8*64*16
#define BR    3
#define MAXPAD 16384         // >= n3 + 3*NN
#define GSTG  8              // leaves staged per chunk in gather (8 * 4KB smem)

// Scratch (device globals: no allocation allowed in kernel_launch)
__device__ float g_y2[1800 * TILE];   // fc(h2), consumed by gather
__device__ int   g_counts[NN];
__device__ int   g_off[NN];           // padded exclusive offsets (multiples of 4)
__device__ int   g_perm[MAXPAD];      // leaf index, ~first for pad slots
__device__ int   g_pad_total;
__device__ __align__(16) int   g_pe[MAXPAD];        // pe3[perm[k]], dense
__device__ __align__(16) float g_scl[MAXPAD * 16];  // scales (0 for pad), dense

// ---- mbarrier / bulk-copy helpers ----
__device__ __forceinline__ uint32_t smem_u32(const void* p) {
    uint32_t a;
    asm("{ .reg .u64 tmp; cvta.to.shared.u64 tmp, %1; cvt.u32.u64 %0, tmp; }"
        : "=r"(a) : "l"(p));
    return a;
}
#define MBARRIER_INIT(mbar, count) \
    asm volatile("mbarrier.init.shared.b64 [%0], %1;" \
                 :: "r"((uint32_t)(mbar)), "r"((uint32_t)(count)) : "memory")
#define MBARRIER_EXPECT_TX(mbar, bytes) \
    asm volatile("mbarrier.arrive.expect_tx.shared.b64 _, [%0], %1;" \
                 :: "r"((uint32_t)(mbar)), "r"((uint32_t)(bytes)) : "memory")
#define MBARRIER_WAIT_PARITY(mbar, parity) do {                                   \
    uint32_t _m = (uint32_t)(mbar); uint32_t _p = (uint32_t)(parity); uint32_t _d; \
    asm volatile("{\n\t.reg .pred p;\n\t"                                         \
        "mbarrier.try_wait.parity.acquire.cta.shared::cta.b64 p, [%1], %2;\n\t"   \
        "selp.b32 %0, 1, 0, p;\n\t}"                                              \
        : "=r"(_d) : "r"(_m), "r"(_p) : "memory");                                \
    if (!_d) {                                                                    \
        asm volatile("{\n\t.reg .pred P1;\n\t"                                    \
            "WAIT_LOOP_%=:\n\t"                                                   \
            "mbarrier.try_wait.parity.acquire.cta.shared::cta.b64 P1, [%0], %1, 0x989680;\n\t" \
            "@P1 bra.uni WAIT_DONE_%=;\n\t"                                       \
            "bra.uni WAIT_LOOP_%=;\n\t"                                           \
            "WAIT_DONE_%=:\n\t}"                                                  \
            :: "r"(_m), "r"(_p) : "memory");                                      \
    }                                                                             \
} while (0)
__device__ __forceinline__ void cp_bulk_g2s(uint32_t smem_dst, const float* gsrc,
                                            uint32_t bytes, uint32_t mbar) {
    size_t gaddr = __cvta_generic_to_global((void*)gsrc);
    asm volatile(
        "cp.async.bulk.shared::cta.global.mbarrier::complete_tx::bytes [%0], [%1], %2, [%3];"
        :: "r"(smem_dst), "l"(gaddr), "r"(bytes), "r"(mbar) : "memory");
}

// One block: counts, padded exclusive-scan offsets, scatter permutation, pad fill.
__global__ void __launch_bounds__(1024) prep_kernel(const int* __restrict__ cn3, int n3) {
    __shared__ int sCnt[2048];
    __shared__ int sScan[2048];
    const int t = threadIdx.x;

    sCnt[t] = 0; sCnt[t + 1024] = 0;
    __syncthreads();
    for (int j = t; j < n3; j += 1024) atomicAdd(&sCnt[cn3[j]], 1);
    __syncthreads();

    // exclusive scan of PADDED counts (pad each to multiple of 4)
    sScan[t]        = (t == 0) ? 0 : ((sCnt[t - 1] + 3) & ~3);
    sScan[t + 1024] = (sCnt[t + 1023] + 3) & ~3;
    __syncthreads();
    for (int d = 1; d < 2048; d <<= 1) {
        int a = sScan[t]        + ((t >= d)        ? sScan[t - d]        : 0);
        int b = sScan[t + 1024] + ((t + 1024 >= d) ? sScan[t + 1024 - d] : 0);
        __syncthreads();
        sScan[t] = a; sScan[t + 1024] = b;
        __syncthreads();
    }

    if (t < NN)        { g_counts[t] = sCnt[t];           g_off[t] = sScan[t]; }
    if (t + 1024 < NN) { g_counts[t+1024] = sCnt[t+1024]; g_off[t+1024] = sScan[t+1024]; }
    if (t == 0) g_pad_total = sScan[NN - 1] + ((sCnt[NN - 1] + 3) & ~3);

    sCnt[t] = 0; sCnt[t + 1024] = 0;
    __syncthreads();
    for (int j = t; j < n3; j += 1024) {
        int c = cn3[j];
        int pos = atomicAdd(&sCnt[c], 1);
        g_perm[sScan[c] + pos] = j;
    }
    __syncthreads();

    // pad fill: duplicate first leaf index, flagged with ~ (scale will be 0)
    for (int i = t; i < NN; i += 1024) {
        int c = g_counts[i];
        if (c == 0) continue;
        int off = g_off[i];
        int pc = (c + 3) & ~3;
        int first = g_perm[off];
        for (int k = c; k < pc; k++) g_perm[off + k] = ~first;
    }
}

// Grid-parallel: resolve all gather-side indirection into dense arrays.
__global__ void __launch_bounds__(256) scale_fill_kernel(
    const float* __restrict__ A, const int* __restrict__ pe3,
    const int* __restrict__ pn3, const int* __restrict__ cn3)
{
    int idx = blockIdx.x * blockDim.x + threadIdx.x;     // over pad_total*16
    if (idx >= g_pad_total * 16) return;
    int k = idx >> 4, f = idx & 15;
    int j = g_perm[k];
    bool pad = (j < 0);
    if (pad) j = ~j;
    g_scl[idx] = pad ? 0.f
                     : A[(size_t)f * NN * NN + (size_t)pn3[j] * NN + (size_t)cn3[j]];
    if (f == 0) g_pe[k] = pe3[j];
}

// fc over 16 features with 4 threads/row: each thread owns 4 contiguous features
// (part = lane&3). Full 16-vector gathered via 3-shfl butterfly within the 4-lane group.
__device__ __forceinline__ void fc4(const float h[4], int part,
                                    const float* __restrict__ sW,
                                    const float* __restrict__ sb, float y[4]) {
    float g1[4], g2[4], g3[4];
    #pragma unroll
    for (int i = 0; i < 4; i++) g1[i] = __shfl_xor_sync(0xffffffffu, h[i], 1);
    #pragma unroll
    for (int i = 0; i < 4; i++) g2[i] = __shfl_xor_sync(0xffffffffu, h[i], 2);
    #pragma unroll
    for (int i = 0; i < 4; i++) g3[i] = __shfl_xor_sync(0xffffffffu, g1[i], 2);
    const int p0 = part * 4;
    const int p1 = (part ^ 1) * 4;
    const int p2 = (part ^ 2) * 4;
    const int p3 = (part ^ 3) * 4;
    #pragma unroll
    for (int f = 0; f < 4; f++) {
        const float* wr = sW + (p0 + f) * 16;
        float acc = sb[p0 + f];
        #pragma unroll
        for (int i = 0; i < 4; i++) acc = fmaf(h[i],  wr[p0 + i], acc);
        #pragma unroll
        for (int i = 0; i < 4; i++) acc = fmaf(g1[i], wr[p1 + i], acc);
        #pragma unroll
        for (int i = 0; i < 4; i++) acc = fmaf(g2[i], wr[p2 + i], acc);
        #pragma unroll
        for (int i = 0; i < 4; i++) acc = fmaf(g3[i], wr[p3 + i], acc);
        y[f] = acc;
    }
}

// Fused levels 0+1: one block per (root, eighth-tile). 256 threads, 4/row (64 rows).
__global__ void __launch_bounds__(256) tree_kernel(
    const float* __restrict__ x, const float* __restrict__ A,
    const float* __restrict__ W, const float* __restrict__ bias,
    const int* __restrict__ root_ids,
    const int* __restrict__ pn1, const int* __restrict__ cn1,
    const int* __restrict__ pn2, const int* __restrict__ cn2)
{
    __shared__ float sW[256];
    __shared__ float sb16[16];
    __shared__ float sS1[3][16];
    __shared__ float sS2[9][16];
    __shared__ int   sCn1[3];
    __shared__ int   sCn2[9];

    const int rp  = blockIdx.x >> 3;
    const int oct = blockIdx.x & 7;
    const int t   = threadIdx.x;

    sW[t] = W[t];
    if (t < 16) sb16[t] = bias[t];
    if (t >= 32 && t < 32 + 48) {            // distinct warps for S1/S2 loads
        int u = t - 32;
        int c = u >> 4, f = u & 15;
        int j1 = rp * 3 + c;
        int pnj = pn1[j1], cnj = cn1[j1];
        sS1[c][f] = A[(size_t)f * NN * NN + (size_t)pnj * NN + (size_t)cnj];
        if (f == 0) sCn1[c] = cnj;
    } else if (t >= 96 && t < 96 + 144) {
        int u = t - 96;
        int c = u >> 4, f = u & 15;
        int j2 = rp * 9 + c;
        int pnj = pn2[j2], cnj = cn2[j2];
        sS2[c][f] = A[(size_t)f * NN * NN + (size_t)pnj * NN + (size_t)cnj];
        if (f == 0) sCn2[c] = cnj;
    }

    const int part = t & 3;
    const int row  = oct * 64 + (t >> 2);
    const size_t roff = (size_t)row * D + part * 4;
    const int fb = part * 4;

    float h[4];
    {
        float4 v = *(const float4*)(x + (size_t)root_ids[rp] * TILE + roff);
        h[0]=v.x; h[1]=v.y; h[2]=v.z; h[3]=v.w;
    }
    __syncthreads();

    float yp[4];
    fc4(h, part, sW, sb16, yp);          // fc(root)

    #pragma unroll 1
    for (int c1 = 0; c1 < 3; c1++) {
        float h1[4];
        {
            float4 v = *(const float4*)(x + (size_t)sCn1[c1] * TILE + roff);
            const float* s1v = &sS1[c1][fb];
            h1[0]=fmaf(yp[0],s1v[0],v.x);
            h1[1]=fmaf(yp[1],s1v[1],v.y);
            h1[2]=fmaf(yp[2],s1v[2],v.z);
            h1[3]=fmaf(yp[3],s1v[3],v.w);
        }
        float y1[4];
        fc4(h1, part, sW, sb16, y1);     // fc(h1) feeds level-2 children

        #pragma unroll
        for (int c2 = 0; c2 < 3; c2++) {
            const int cc = c1 * 3 + c2;
            float h2[4];
            {
                float4 v = *(const float4*)(x + (size_t)sCn2[cc] * TILE + roff);
                const float* s2v = &sS2[cc][fb];
                h2[0]=fmaf(y1[0],s2v[0],v.x);
                h2[1]=fmaf(y1[1],s2v[1],v.y);
                h2[2]=fmaf(y1[2],s2v[2],v.z);
                h2[3]=fmaf(y1[3],s2v[3],v.w);
            }
            float y2v[4];
            fc4(h2, part, sW, sb16, y2v); // store fc(h2) for gather

            *(float4*)(g_y2 + ((size_t)rp * 9 + cc) * TILE + roff) =
                make_float4(y2v[0], y2v[1], y2v[2], y2v[3]);
        }
    }
}

// Eighth-tile blocks, 128 threads. y2 slices arrive via cp.async.bulk into smem
// (bulk engine: no per-line L1tex wavefront replays, no 1.82cyc/LDG LSU floor).
// Compute reads conflict-free scalar LDS; feat = t&15 is lane-constant -> one
// broadcast scale load per leaf. x/out stay striped __ldcs/__stcs.
__global__ void __launch_bounds__(128) gather_kernel(
    const float* __restrict__ x, float* __restrict__ out)
{
    extern __shared__ __align__(16) float s_buf[];   // GSTG*1024 floats + mbar

    const int node = blockIdx.x >> 3;
    const int oct  = blockIdx.x & 7;
    const int t    = threadIdx.x;

    const int cnt = g_counts[node];
    const size_t sbase = (size_t)node * TILE + (size_t)oct * 1024 + t;

    float xv[8];
    #pragma unroll
    for (int j = 0; j < 8; j++) xv[j] = __ldcs(x + sbase + j * 128);

    if (cnt > 0) {
        const uint32_t smb  = smem_u32(s_buf);
        const uint32_t mbar = smb + GSTG * 4096;
        if (t == 0) MBARRIER_INIT(mbar, 1);
        __syncthreads();

        float acc[8];
        #pragma unroll
        for (int j = 0; j < 8; j++) acc[j] = 0.f;

        const int off  = g_off[node];        // multiple of 4
        const int pc   = (cnt + 3) & ~3;
        const int feat = t & 15;
        const size_t yoff = (size_t)oct * 1024;

        int phase = 0;
        for (int base = 0; base < pc; base += GSTG, phase ^= 1) {
            const int m = min(GSTG, pc - base);
            if (t == 0) {
                // batch pe loads (independent), then issue bulk copies
                int4 p0 = *(const int4*)(g_pe + off + base);
                int4 p1 = *(const int4*)(g_pe + off + base + 4); // safe over-read
                int pes[8] = {p0.x, p0.y, p0.z, p0.w, p1.x, p1.y, p1.z, p1.w};
                MBARRIER_EXPECT_TX(mbar, (uint32_t)m * 4096u);
                #pragma unroll
                for (int i = 0; i < GSTG; i++) {
                    if (i < m)
                        cp_bulk_g2s(smb + i * 4096,
                                    g_y2 + (size_t)pes[i] * TILE + yoff,
                                    4096u, mbar);
                }
            }
            MBARRIER_WAIT_PARITY(mbar, phase);

            for (int i = 0; i < m; i++) {
                const float s = g_scl[(size_t)(off + base + i) * 16 + feat];
                const float* yb = s_buf + i * 1024 + t;
                #pragma unroll
                for (int j = 0; j < 8; j++) acc[j] = fmaf(yb[j * 128], s, acc[j]);
            }
            __syncthreads();   // all reads done before buffers are reused
        }

        const float inv = 1.0f / (float)cnt;
        #pragma unroll
        for (int j = 0; j < 8; j++) xv[j] = fmaf(acc[j], inv, xv[j]);
    }

    #pragma unroll
    for (int j = 0; j < 8; j++) __stcs(out + sbase + j * 128, xv[j]);
}

extern "C" void kernel_launch(void* const* d_in, const int* in_sizes, int n_in,
                              void* d_out, int out_size) {
    const float* x    = (const float*)d_in[0];
    const float* A    = (const float*)d_in[1];
    const float* W    = (const float*)d_in[2];
    const float* b    = (const float*)d_in[3];
    const int*   root = (const int*)d_in[4];
    const int*   pn1  = (const int*)d_in[6];
    const int*   cn1  = (const int*)d_in[7];
    const int*   pn2  = (const int*)d_in[9];
    const int*   cn2  = (const int*)d_in[10];
    const int*   pe3  = (const int*)d_in[11];
    const int*   pn3  = (const int*)d_in[12];
    const int*   cn3  = (const int*)d_in[13];
    float* out = (float*)d_out;

    const int n1 = in_sizes[5];    // 600
    const int n3 = in_sizes[11];   // 5400
    const int n_roots = n1 / BR;   // 200

    const int gather_smem = GSTG * 4096 + 128;   // stage buffers + mbarrier

    static cudaStream_t s_side = nullptr;
    static cudaEvent_t  ev_fork = nullptr, ev_join = nullptr;
    if (!s_side) {
        cudaStreamCreateWithFlags(&s_side, cudaStreamNonBlocking);
        cudaEventCreateWithFlags(&ev_fork, cudaEventDisableTiming);
        cudaEventCreateWithFlags(&ev_join, cudaEventDisableTiming);
        cudaFuncSetAttribute(gather_kernel,
                             cudaFuncAttributeMaxDynamicSharedMemorySize,
                             gather_smem);
    }

    // prep + scale resolve only feed gather; run them concurrently with tree_kernel.
    cudaEventRecord(ev_fork, 0);
    cudaStreamWaitEvent(s_side, ev_fork, 0);
    prep_kernel<<<1, 1024, 0, s_side>>>(cn3, n3);
    const int padmax = n3 + 3 * NN;
    scale_fill_kernel<<<(padmax * 16 + 255) / 256, 256, 0, s_side>>>(A, pe3, pn3, cn3);
    cudaEventRecord(ev_join, s_side);

    tree_kernel<<<8 * n_roots, 256>>>(x, A, W, b, root, pn1, cn1, pn2, cn2);

    cudaStreamWaitEvent(0, ev_join, 0);
    gather_kernel<<<8 * NN, 128, gather_smem>>>(x, out);
}

// round 15
// speedup vs baseline: 1.1934x; 1.1934x over previous
#include <cuda_runtime.h>
#include <cstdint>

#define NN    2000
#define D     16
#define TILE  8192           // B*T*D = 8*64*16
#define BR    3
#define MAXPAD 16384         // >= n3 + 3*NN

// Scratch (device globals: no allocation allowed in kernel_launch)
__device__ float g_y2[1800 * TILE];   // fc(h2), consumed by gather
__device__ int   g_counts[NN];
__device__ int   g_off[NN];           // padded exclusive offsets (multiples of 4)
__device__ int   g_perm[MAXPAD];      // leaf index, ~first for pad slots
__device__ int   g_pad_total;
__device__ __align__(16) int   g_pe[MAXPAD];        // pe3[perm[k]], dense
__device__ __align__(16) float g_scl[MAXPAD * 16];  // scales (0 for pad), dense

// One block: counts, padded exclusive-scan offsets, scatter permutation, pad fill.
__global__ void __launch_bounds__(1024) prep_kernel(const int* __restrict__ cn3, int n3) {
    __shared__ int sCnt[2048];
    __shared__ int sScan[2048];
    const int t = threadIdx.x;

    sCnt[t] = 0; sCnt[t + 1024] = 0;
    __syncthreads();
    for (int j = t; j < n3; j += 1024) atomicAdd(&sCnt[cn3[j]], 1);
    __syncthreads();

    // exclusive scan of PADDED counts (pad each to multiple of 4)
    sScan[t]        = (t == 0) ? 0 : ((sCnt[t - 1] + 3) & ~3);
    sScan[t + 1024] = (sCnt[t + 1023] + 3) & ~3;
    __syncthreads();
    for (int d = 1; d < 2048; d <<= 1) {
        int a = sScan[t]        + ((t >= d)        ? sScan[t - d]        : 0);
        int b = sScan[t + 1024] + ((t + 1024 >= d) ? sScan[t + 1024 - d] : 0);
        __syncthreads();
        sScan[t] = a; sScan[t + 1024] = b;
        __syncthreads();
    }

    if (t < NN)        { g_counts[t] = sCnt[t];           g_off[t] = sScan[t]; }
    if (t + 1024 < NN) { g_counts[t+1024] = sCnt[t+1024]; g_off[t+1024] = sScan[t+1024]; }
    if (t == 0) g_pad_total = sScan[NN - 1] + ((sCnt[NN - 1] + 3) & ~3);

    sCnt[t] = 0; sCnt[t + 1024] = 0;
    __syncthreads();
    for (int j = t; j < n3; j += 1024) {
        int c = cn3[j];
        int pos = atomicAdd(&sCnt[c], 1);
        g_perm[sScan[c] + pos] = j;
    }
    __syncthreads();

    // pad fill: duplicate first leaf index, flagged with ~ (scale will be 0)
    for (int i = t; i < NN; i += 1024) {
        int c = g_counts[i];
        if (c == 0) continue;
        int off = g_off[i];
        int pc = (c + 3) & ~3;
        int first = g_perm[off];
        for (int k = c; k < pc; k++) g_perm[off + k] = ~first;
    }
}

// Grid-parallel: resolve all gather-side indirection into dense arrays.
__global__ void __launch_bounds__(256) scale_fill_kernel(
    const float* __restrict__ A, const int* __restrict__ pe3,
    const int* __restrict__ pn3, const int* __restrict__ cn3)
{
    int idx = blockIdx.x * blockDim.x + threadIdx.x;     // over pad_total*16
    if (idx >= g_pad_total * 16) return;
    int k = idx >> 4, f = idx & 15;
    int j = g_perm[k];
    bool pad = (j < 0);
    if (pad) j = ~j;
    g_scl[idx] = pad ? 0.f
                     : A[(size_t)f * NN * NN + (size_t)pn3[j] * NN + (size_t)cn3[j]];
    if (f == 0) g_pe[k] = pe3[j];
}

// fc over 16 features with 4 threads/row: each thread owns 4 contiguous features
// (part = lane&3). Full 16-vector gathered via 3-shfl butterfly within the 4-lane group.
__device__ __forceinline__ void fc4(const float h[4], int part,
                                    const float* __restrict__ sW,
                                    const float* __restrict__ sb, float y[4]) {
    float g1[4], g2[4], g3[4];
    #pragma unroll
    for (int i = 0; i < 4; i++) g1[i] = __shfl_xor_sync(0xffffffffu, h[i], 1);
    #pragma unroll
    for (int i = 0; i < 4; i++) g2[i] = __shfl_xor_sync(0xffffffffu, h[i], 2);
    #pragma unroll
    for (int i = 0; i < 4; i++) g3[i] = __shfl_xor_sync(0xffffffffu, g1[i], 2);
    const int p0 = part * 4;
    const int p1 = (part ^ 1) * 4;
    const int p2 = (part ^ 2) * 4;
    const int p3 = (part ^ 3) * 4;
    #pragma unroll
    for (int f = 0; f < 4; f++) {
        const float* wr = sW + (p0 + f) * 16;
        float acc = sb[p0 + f];
        #pragma unroll
        for (int i = 0; i < 4; i++) acc = fmaf(h[i],  wr[p0 + i], acc);
        #pragma unroll
        for (int i = 0; i < 4; i++) acc = fmaf(g1[i], wr[p1 + i], acc);
        #pragma unroll
        for (int i = 0; i < 4; i++) acc = fmaf(g2[i], wr[p2 + i], acc);
        #pragma unroll
        for (int i = 0; i < 4; i++) acc = fmaf(g3[i], wr[p3 + i], acc);
        y[f] = acc;
    }
}

// Fused levels 0+1: one block per (root, eighth-tile). 256 threads, 4/row (64 rows).
// c1 loop fully unrolled: 4-wide per-thread state keeps the live set affordable
// while giving ptxas 3 independent subtree chains to interleave.
__global__ void __launch_bounds__(256) tree_kernel(
    const float* __restrict__ x, const float* __restrict__ A,
    const float* __restrict__ W, const float* __restrict__ bias,
    const int* __restrict__ root_ids,
    const int* __restrict__ pn1, const int* __restrict__ cn1,
    const int* __restrict__ pn2, const int* __restrict__ cn2)
{
    __shared__ float sW[256];
    __shared__ float sb16[16];
    __shared__ float sS1[3][16];
    __shared__ float sS2[9][16];
    __shared__ int   sCn1[3];
    __shared__ int   sCn2[9];

    const int rp  = blockIdx.x >> 3;
    const int oct = blockIdx.x & 7;
    const int t   = threadIdx.x;

    sW[t] = W[t];
    if (t < 16) sb16[t] = bias[t];
    if (t >= 32 && t < 32 + 48) {            // distinct warps for S1/S2 loads
        int u = t - 32;
        int c = u >> 4, f = u & 15;
        int j1 = rp * 3 + c;
        int pnj = pn1[j1], cnj = cn1[j1];
        sS1[c][f] = A[(size_t)f * NN * NN + (size_t)pnj * NN + (size_t)cnj];
        if (f == 0) sCn1[c] = cnj;
    } else if (t >= 96 && t < 96 + 144) {
        int u = t - 96;
        int c = u >> 4, f = u & 15;
        int j2 = rp * 9 + c;
        int pnj = pn2[j2], cnj = cn2[j2];
        sS2[c][f] = A[(size_t)f * NN * NN + (size_t)pnj * NN + (size_t)cnj];
        if (f == 0) sCn2[c] = cnj;
    }

    const int part = t & 3;
    const int row  = oct * 64 + (t >> 2);
    const size_t roff = (size_t)row * D + part * 4;
    const int fb = part * 4;

    float h[4];
    {
        float4 v = *(const float4*)(x + (size_t)root_ids[rp] * TILE + roff);
        h[0]=v.x; h[1]=v.y; h[2]=v.z; h[3]=v.w;
    }
    __syncthreads();

    float yp[4];
    fc4(h, part, sW, sb16, yp);          // fc(root)

    #pragma unroll
    for (int c1 = 0; c1 < 3; c1++) {
        float h1[4];
        {
            float4 v = *(const float4*)(x + (size_t)sCn1[c1] * TILE + roff);
            const float* s1v = &sS1[c1][fb];
            h1[0]=fmaf(yp[0],s1v[0],v.x);
            h1[1]=fmaf(yp[1],s1v[1],v.y);
            h1[2]=fmaf(yp[2],s1v[2],v.z);
            h1[3]=fmaf(yp[3],s1v[3],v.w);
        }
        float y1[4];
        fc4(h1, part, sW, sb16, y1);     // fc(h1) feeds level-2 children

        #pragma unroll
        for (int c2 = 0; c2 < 3; c2++) {
            const int cc = c1 * 3 + c2;
            float h2[4];
            {
                float4 v = *(const float4*)(x + (size_t)sCn2[cc] * TILE + roff);
                const float* s2v = &sS2[cc][fb];
                h2[0]=fmaf(y1[0],s2v[0],v.x);
                h2[1]=fmaf(y1[1],s2v[1],v.y);
                h2[2]=fmaf(y1[2],s2v[2],v.z);
                h2[3]=fmaf(y1[3],s2v[3],v.w);
            }
            float y2v[4];
            fc4(h2, part, sW, sb16, y2v); // store fc(h2) for gather

            *(float4*)(g_y2 + ((size_t)rp * 9 + cc) * TILE + roff) =
                make_float4(y2v[0], y2v[1], y2v[2], y2v[3]);
        }
    }
}

// Eighth-tile blocks, 128 threads, 2/row. Direct node indexing (best-measured config).
// Padded 4-wide leaf loop; dense scales; no smem/sync; streaming hints.
__global__ void __launch_bounds__(128) gather_kernel(
    const float* __restrict__ x, float* __restrict__ out)
{
    const int node = blockIdx.x >> 3;
    const int oct  = blockIdx.x & 7;
    const int t    = threadIdx.x;
    const int row  = oct * 64 + (t >> 1);
    const int part = (t & 1) * 8;

    const int cnt = g_counts[node];
    const size_t eoff = (size_t)node * TILE + (size_t)row * D + part;
    const float4* xr = (const float4*)(x + eoff);
    float4 o0 = __ldcs(xr);       // x tile: single use, evict-first
    float4 o1 = __ldcs(xr + 1);

    if (cnt > 0) {
        float acc[8];
        #pragma unroll
        for (int f = 0; f < 8; f++) acc[f] = 0.f;
        const int off = g_off[node];          // multiple of 4
        const int pc  = (cnt + 3) & ~3;
        const size_t roff = (size_t)row * D + part;

        for (int k = 0; k < pc; k += 4) {
            const int4 pe4 = *(const int4*)(g_pe + off + k);
            const float4* p0 = (const float4*)(g_y2 + (size_t)pe4.x * TILE + roff);
            const float4* p1 = (const float4*)(g_y2 + (size_t)pe4.y * TILE + roff);
            const float4* p2 = (const float4*)(g_y2 + (size_t)pe4.z * TILE + roff);
            const float4* p3 = (const float4*)(g_y2 + (size_t)pe4.w * TILE + roff);
            float4 a0 = p0[0], a1 = p0[1];
            float4 b0 = p1[0], b1 = p1[1];
            float4 c0 = p2[0], c1 = p2[1];
            float4 d0 = p3[0], d1 = p3[1];

            const float4* sp = (const float4*)(g_scl + (size_t)(off + k) * 16 + part);
            // leaf i scales at sp + i*4 (16 floats per leaf = 4 float4)
            float4 s0a = sp[0],  s0b = sp[1];
            float4 s1a = sp[4],  s1b = sp[5];
            float4 s2a = sp[8],  s2b = sp[9];
            float4 s3a = sp[12], s3b = sp[13];

            acc[0]=fmaf(a0.x,s0a.x,acc[0]); acc[1]=fmaf(a0.y,s0a.y,acc[1]);
            acc[2]=fmaf(a0.z,s0a.z,acc[2]); acc[3]=fmaf(a0.w,s0a.w,acc[3]);
            acc[4]=fmaf(a1.x,s0b.x,acc[4]); acc[5]=fmaf(a1.y,s0b.y,acc[5]);
            acc[6]=fmaf(a1.z,s0b.z,acc[6]); acc[7]=fmaf(a1.w,s0b.w,acc[7]);

            acc[0]=fmaf(b0.x,s1a.x,acc[0]); acc[1]=fmaf(b0.y,s1a.y,acc[1]);
            acc[2]=fmaf(b0.z,s1a.z,acc[2]); acc[3]=fmaf(b0.w,s1a.w,acc[3]);
            acc[4]=fmaf(b1.x,s1b.x,acc[4]); acc[5]=fmaf(b1.y,s1b.y,acc[5]);
            acc[6]=fmaf(b1.z,s1b.z,acc[6]); acc[7]=fmaf(b1.w,s1b.w,acc[7]);

            acc[0]=fmaf(c0.x,s2a.x,acc[0]); acc[1]=fmaf(c0.y,s2a.y,acc[1]);
            acc[2]=fmaf(c0.z,s2a.z,acc[2]); acc[3]=fmaf(c0.w,s2a.w,acc[3]);
            acc[4]=fmaf(c1.x,s2b.x,acc[4]); acc[5]=fmaf(c1.y,s2b.y,acc[5]);
            acc[6]=fmaf(c1.z,s2b.z,acc[6]); acc[7]=fmaf(c1.w,s2b.w,acc[7]);

            acc[0]=fmaf(d0.x,s3a.x,acc[0]); acc[1]=fmaf(d0.y,s3a.y,acc[1]);
            acc[2]=fmaf(d0.z,s3a.z,acc[2]); acc[3]=fmaf(d0.w,s3a.w,acc[3]);
            acc[4]=fmaf(d1.x,s3b.x,acc[4]); acc[5]=fmaf(d1.y,s3b.y,acc[5]);
            acc[6]=fmaf(d1.z,s3b.z,acc[6]); acc[7]=fmaf(d1.w,s3b.w,acc[7]);
        }
        const float inv = 1.0f / (float)cnt;
        o0.x += acc[0]*inv; o0.y += acc[1]*inv; o0.z += acc[2]*inv; o0.w += acc[3]*inv;
        o1.x += acc[4]*inv; o1.y += acc[5]*inv; o1.z += acc[6]*inv; o1.w += acc[7]*inv;
    }

    float4* dst = (float4*)(out + eoff);
    __stcs(dst,     o0);          // out: never re-read, evict-first
    __stcs(dst + 1, o1);
}

extern "C" void kernel_launch(void* const* d_in, const int* in_sizes, int n_in,
                              void* d_out, int out_size) {
    const float* x    = (const float*)d_in[0];
    const float* A    = (const float*)d_in[1];
    const float* W    = (const float*)d_in[2];
    const float* b    = (const float*)d_in[3];
    const int*   root = (const int*)d_in[4];
    const int*   pn1  = (const int*)d_in[6];
    const int*   cn1  = (const int*)d_in[7];
    const int*   pn2  = (const int*)d_in[9];
    const int*   cn2  = (const int*)d_in[10];
    const int*   pe3  = (const int*)d_in[11];
    const int*   pn3  = (const int*)d_in[12];
    const int*   cn3  = (const int*)d_in[13];
    float* out = (float*)d_out;

    const int n1 = in_sizes[5];    // 600
    const int n3 = in_sizes[11];   // 5400
    const int n_roots = n1 / BR;   // 200

    static cudaStream_t s_side = nullptr;
    static cudaEvent_t  ev_fork = nullptr, ev_join = nullptr;
    if (!s_side) {
        cudaStreamCreateWithFlags(&s_side, cudaStreamNonBlocking);
        cudaEventCreateWithFlags(&ev_fork, cudaEventDisableTiming);
        cudaEventCreateWithFlags(&ev_join, cudaEventDisableTiming);
    }

    // prep + scale resolve only feed gather; run them concurrently with tree_kernel.
    cudaEventRecord(ev_fork, 0);
    cudaStreamWaitEvent(s_side, ev_fork, 0);
    prep_kernel<<<1, 1024, 0, s_side>>>(cn3, n3);
    const int padmax = n3 + 3 * NN;
    scale_fill_kernel<<<(padmax * 16 + 255) / 256, 256, 0, s_side>>>(A, pe3, pn3, cn3);
    cudaEventRecord(ev_join, s_side);

    tree_kernel<<<8 * n_roots, 256>>>(x, A, W, b, root, pn1, cn1, pn2, cn2);

    cudaStreamWaitEvent(0, ev_join, 0);
    gather_kernel<<<8 * NN, 128>>>(x, out);
}

// round 16
// speedup vs baseline: 1.2837x; 1.0757x over previous
#include <cuda_runtime.h>
#include <cstdint>

#define NN    2000
#define D     16
#define TILE  8192           // B*T*D = 8*64*16
#define BR    3
#define MAXPAD 16384         // >= n3 + 3*NN

// Scratch (device globals: no allocation allowed in kernel_launch)
__device__ float g_y2[1800 * TILE];   // fc(h2), consumed by gather
__device__ int   g_counts[NN];
__device__ int   g_off[NN];           // padded exclusive offsets (multiples of 4)
__device__ int   g_perm[MAXPAD];      // leaf index, ~first for pad slots
__device__ int   g_pad_total;
__device__ __align__(16) int   g_pe[MAXPAD];        // pe3[perm[k]], dense
__device__ __align__(16) float g_scl[MAXPAD * 16];  // scales (0 for pad), dense

// One block: counts, padded exclusive-scan offsets, scatter permutation, pad fill.
__global__ void __launch_bounds__(1024) prep_kernel(const int* __restrict__ cn3, int n3) {
    __shared__ int sCnt[2048];
    __shared__ int sScan[2048];
    const int t = threadIdx.x;

    sCnt[t] = 0; sCnt[t + 1024] = 0;
    __syncthreads();
    for (int j = t; j < n3; j += 1024) atomicAdd(&sCnt[cn3[j]], 1);
    __syncthreads();

    // exclusive scan of PADDED counts (pad each to multiple of 4)
    sScan[t]        = (t == 0) ? 0 : ((sCnt[t - 1] + 3) & ~3);
    sScan[t + 1024] = (sCnt[t + 1023] + 3) & ~3;
    __syncthreads();
    for (int d = 1; d < 2048; d <<= 1) {
        int a = sScan[t]        + ((t >= d)        ? sScan[t - d]        : 0);
        int b = sScan[t + 1024] + ((t + 1024 >= d) ? sScan[t + 1024 - d] : 0);
        __syncthreads();
        sScan[t] = a; sScan[t + 1024] = b;
        __syncthreads();
    }

    if (t < NN)        { g_counts[t] = sCnt[t];           g_off[t] = sScan[t]; }
    if (t + 1024 < NN) { g_counts[t+1024] = sCnt[t+1024]; g_off[t+1024] = sScan[t+1024]; }
    if (t == 0) g_pad_total = sScan[NN - 1] + ((sCnt[NN - 1] + 3) & ~3);

    sCnt[t] = 0; sCnt[t + 1024] = 0;
    __syncthreads();
    for (int j = t; j < n3; j += 1024) {
        int c = cn3[j];
        int pos = atomicAdd(&sCnt[c], 1);
        g_perm[sScan[c] + pos] = j;
    }
    __syncthreads();

    // pad fill: duplicate first leaf index, flagged with ~ (scale will be 0)
    for (int i = t; i < NN; i += 1024) {
        int c = g_counts[i];
        if (c == 0) continue;
        int off = g_off[i];
        int pc = (c + 3) & ~3;
        int first = g_perm[off];
        for (int k = c; k < pc; k++) g_perm[off + k] = ~first;
    }
}

// Grid-parallel: resolve all gather-side indirection into dense arrays.
__global__ void __launch_bounds__(256) scale_fill_kernel(
    const float* __restrict__ A, const int* __restrict__ pe3,
    const int* __restrict__ pn3, const int* __restrict__ cn3)
{
    int idx = blockIdx.x * blockDim.x + threadIdx.x;     // over pad_total*16
    if (idx >= g_pad_total * 16) return;
    int k = idx >> 4, f = idx & 15;
    int j = g_perm[k];
    bool pad = (j < 0);
    if (pad) j = ~j;
    g_scl[idx] = pad ? 0.f
                     : A[(size_t)f * NN * NN + (size_t)pn3[j] * NN + (size_t)cn3[j]];
    if (f == 0) g_pe[k] = pe3[j];
}

// fc over 16 features with 4 threads/row: each thread owns 4 contiguous features
// (part = lane&3). Full 16-vector gathered via 3-shfl butterfly within the 4-lane group.
__device__ __forceinline__ void fc4(const float h[4], int part,
                                    const float* __restrict__ sW,
                                    const float* __restrict__ sb, float y[4]) {
    float g1[4], g2[4], g3[4];
    #pragma unroll
    for (int i = 0; i < 4; i++) g1[i] = __shfl_xor_sync(0xffffffffu, h[i], 1);
    #pragma unroll
    for (int i = 0; i < 4; i++) g2[i] = __shfl_xor_sync(0xffffffffu, h[i], 2);
    #pragma unroll
    for (int i = 0; i < 4; i++) g3[i] = __shfl_xor_sync(0xffffffffu, g1[i], 2);
    const int p0 = part * 4;
    const int p1 = (part ^ 1) * 4;
    const int p2 = (part ^ 2) * 4;
    const int p3 = (part ^ 3) * 4;
    #pragma unroll
    for (int f = 0; f < 4; f++) {
        const float* wr = sW + (p0 + f) * 16;
        float acc = sb[p0 + f];
        #pragma unroll
        for (int i = 0; i < 4; i++) acc = fmaf(h[i],  wr[p0 + i], acc);
        #pragma unroll
        for (int i = 0; i < 4; i++) acc = fmaf(g1[i], wr[p1 + i], acc);
        #pragma unroll
        for (int i = 0; i < 4; i++) acc = fmaf(g2[i], wr[p2 + i], acc);
        #pragma unroll
        for (int i = 0; i < 4; i++) acc = fmaf(g3[i], wr[p3 + i], acc);
        y[f] = acc;
    }
}

// Fused levels 0+1: one block per (root, eighth-tile). 256 threads, 4/row (64 rows).
// c1 loop fully unrolled (R15 WIN config).
__global__ void __launch_bounds__(256) tree_kernel(
    const float* __restrict__ x, const float* __restrict__ A,
    const float* __restrict__ W, const float* __restrict__ bias,
    const int* __restrict__ root_ids,
    const int* __restrict__ pn1, const int* __restrict__ cn1,
    const int* __restrict__ pn2, const int* __restrict__ cn2)
{
    __shared__ float sW[256];
    __shared__ float sb16[16];
    __shared__ float sS1[3][16];
    __shared__ float sS2[9][16];
    __shared__ int   sCn1[3];
    __shared__ int   sCn2[9];

    const int rp  = blockIdx.x >> 3;
    const int oct = blockIdx.x & 7;
    const int t   = threadIdx.x;

    sW[t] = W[t];
    if (t < 16) sb16[t] = bias[t];
    if (t >= 32 && t < 32 + 48) {            // distinct warps for S1/S2 loads
        int u = t - 32;
        int c = u >> 4, f = u & 15;
        int j1 = rp * 3 + c;
        int pnj = pn1[j1], cnj = cn1[j1];
        sS1[c][f] = A[(size_t)f * NN * NN + (size_t)pnj * NN + (size_t)cnj];
        if (f == 0) sCn1[c] = cnj;
    } else if (t >= 96 && t < 96 + 144) {
        int u = t - 96;
        int c = u >> 4, f = u & 15;
        int j2 = rp * 9 + c;
        int pnj = pn2[j2], cnj = cn2[j2];
        sS2[c][f] = A[(size_t)f * NN * NN + (size_t)pnj * NN + (size_t)cnj];
        if (f == 0) sCn2[c] = cnj;
    }

    const int part = t & 3;
    const int row  = oct * 64 + (t >> 2);
    const size_t roff = (size_t)row * D + part * 4;
    const int fb = part * 4;

    float h[4];
    {
        float4 v = *(const float4*)(x + (size_t)root_ids[rp] * TILE + roff);
        h[0]=v.x; h[1]=v.y; h[2]=v.z; h[3]=v.w;
    }
    __syncthreads();

    float yp[4];
    fc4(h, part, sW, sb16, yp);          // fc(root)

    #pragma unroll
    for (int c1 = 0; c1 < 3; c1++) {
        float h1[4];
        {
            float4 v = *(const float4*)(x + (size_t)sCn1[c1] * TILE + roff);
            const float* s1v = &sS1[c1][fb];
            h1[0]=fmaf(yp[0],s1v[0],v.x);
            h1[1]=fmaf(yp[1],s1v[1],v.y);
            h1[2]=fmaf(yp[2],s1v[2],v.z);
            h1[3]=fmaf(yp[3],s1v[3],v.w);
        }
        float y1[4];
        fc4(h1, part, sW, sb16, y1);     // fc(h1) feeds level-2 children

        #pragma unroll
        for (int c2 = 0; c2 < 3; c2++) {
            const int cc = c1 * 3 + c2;
            float h2[4];
            {
                float4 v = *(const float4*)(x + (size_t)sCn2[cc] * TILE + roff);
                const float* s2v = &sS2[cc][fb];
                h2[0]=fmaf(y1[0],s2v[0],v.x);
                h2[1]=fmaf(y1[1],s2v[1],v.y);
                h2[2]=fmaf(y1[2],s2v[2],v.z);
                h2[3]=fmaf(y1[3],s2v[3],v.w);
            }
            float y2v[4];
            fc4(h2, part, sW, sb16, y2v); // store fc(h2) for gather

            *(float4*)(g_y2 + ((size_t)rp * 9 + cc) * TILE + roff) =
                make_float4(y2v[0], y2v[1], y2v[2], y2v[3]);
        }
    }
}

// Eighth-tile blocks, 128 threads. DENSE mapping: lane l of warp w owns elements
// {w*256 + l*4, w*256 + 128 + l*4} -> every LDG.128 covers 4 FULL cache lines
// (halves L1 wavefront replays vs the old interleaved 8-half-line pattern).
// e1-e0 = 128 == 0 mod 16, so both float4s share features -> ONE scale float4/leaf.
__global__ void __launch_bounds__(128) gather_kernel(
    const float* __restrict__ x, float* __restrict__ out)
{
    const int node = blockIdx.x >> 3;
    const int oct  = blockIdx.x & 7;
    const int t    = threadIdx.x;
    const int w    = t >> 5;
    const int l    = t & 31;

    const int e0 = w * 256 + l * 4;     // dense 512B per warp-LDG
    const int e1 = e0 + 128;
    const int fb = (l * 4) & 15;        // feature base, same for e0 and e1

    const int cnt = g_counts[node];
    const size_t base = (size_t)node * TILE + (size_t)oct * 1024;

    float4 o0 = __ldcs((const float4*)(x + base + e0));
    float4 o1 = __ldcs((const float4*)(x + base + e1));

    if (cnt > 0) {
        float4 acc0 = make_float4(0.f, 0.f, 0.f, 0.f);
        float4 acc1 = make_float4(0.f, 0.f, 0.f, 0.f);
        const int off = g_off[node];          // multiple of 4
        const int pc  = (cnt + 3) & ~3;
        const size_t yoff = (size_t)oct * 1024;

        for (int k = 0; k < pc; k += 4) {
            const int4 pe4 = *(const int4*)(g_pe + off + k);
            const float* b0 = g_y2 + (size_t)pe4.x * TILE + yoff;
            const float* b1 = g_y2 + (size_t)pe4.y * TILE + yoff;
            const float* b2 = g_y2 + (size_t)pe4.z * TILE + yoff;
            const float* b3 = g_y2 + (size_t)pe4.w * TILE + yoff;

            float4 a0 = *(const float4*)(b0 + e0), a1 = *(const float4*)(b0 + e1);
            float4 c0 = *(const float4*)(b1 + e0), c1 = *(const float4*)(b1 + e1);
            float4 d0 = *(const float4*)(b2 + e0), d1 = *(const float4*)(b2 + e1);
            float4 f0 = *(const float4*)(b3 + e0), f1 = *(const float4*)(b3 + e1);

            float4 s0 = *(const float4*)(g_scl + (size_t)(off + k + 0) * 16 + fb);
            float4 s1 = *(const float4*)(g_scl + (size_t)(off + k + 1) * 16 + fb);
            float4 s2 = *(const float4*)(g_scl + (size_t)(off + k + 2) * 16 + fb);
            float4 s3 = *(const float4*)(g_scl + (size_t)(off + k + 3) * 16 + fb);

            acc0.x=fmaf(a0.x,s0.x,acc0.x); acc0.y=fmaf(a0.y,s0.y,acc0.y);
            acc0.z=fmaf(a0.z,s0.z,acc0.z); acc0.w=fmaf(a0.w,s0.w,acc0.w);
            acc1.x=fmaf(a1.x,s0.x,acc1.x); acc1.y=fmaf(a1.y,s0.y,acc1.y);
            acc1.z=fmaf(a1.z,s0.z,acc1.z); acc1.w=fmaf(a1.w,s0.w,acc1.w);

            acc0.x=fmaf(c0.x,s1.x,acc0.x); acc0.y=fmaf(c0.y,s1.y,acc0.y);
            acc0.z=fmaf(c0.z,s1.z,acc0.z); acc0.w=fmaf(c0.w,s1.w,acc0.w);
            acc1.x=fmaf(c1.x,s1.x,acc1.x); acc1.y=fmaf(c1.y,s1.y,acc1.y);
            acc1.z=fmaf(c1.z,s1.z,acc1.z); acc1.w=fmaf(c1.w,s1.w,acc1.w);

            acc0.x=fmaf(d0.x,s2.x,acc0.x); acc0.y=fmaf(d0.y,s2.y,acc0.y);
            acc0.z=fmaf(d0.z,s2.z,acc0.z); acc0.w=fmaf(d0.w,s2.w,acc0.w);
            acc1.x=fmaf(d1.x,s2.x,acc1.x); acc1.y=fmaf(d1.y,s2.y,acc1.y);
            acc1.z=fmaf(d1.z,s2.z,acc1.z); acc1.w=fmaf(d1.w,s2.w,acc1.w);

            acc0.x=fmaf(f0.x,s3.x,acc0.x); acc0.y=fmaf(f0.y,s3.y,acc0.y);
            acc0.z=fmaf(f0.z,s3.z,acc0.z); acc0.w=fmaf(f0.w,s3.w,acc0.w);
            acc1.x=fmaf(f1.x,s3.x,acc1.x); acc1.y=fmaf(f1.y,s3.y,acc1.y);
            acc1.z=fmaf(f1.z,s3.z,acc1.z); acc1.w=fmaf(f1.w,s3.w,acc1.w);
        }
        const float inv = 1.0f / (float)cnt;
        o0.x = fmaf(acc0.x, inv, o0.x); o0.y = fmaf(acc0.y, inv, o0.y);
        o0.z = fmaf(acc0.z, inv, o0.z); o0.w = fmaf(acc0.w, inv, o0.w);
        o1.x = fmaf(acc1.x, inv, o1.x); o1.y = fmaf(acc1.y, inv, o1.y);
        o1.z = fmaf(acc1.z, inv, o1.z); o1.w = fmaf(acc1.w, inv, o1.w);
    }

    __stcs((float4*)(out + base + e0), o0);
    __stcs((float4*)(out + base + e1), o1);
}

extern "C" void kernel_launch(void* const* d_in, const int* in_sizes, int n_in,
                              void* d_out, int out_size) {
    const float* x    = (const float*)d_in[0];
    const float* A    = (const float*)d_in[1];
    const float* W    = (const float*)d_in[2];
    const float* b    = (const float*)d_in[3];
    const int*   root = (const int*)d_in[4];
    const int*   pn1  = (const int*)d_in[6];
    const int*   cn1  = (const int*)d_in[7];
    const int*   pn2  = (const int*)d_in[9];
    const int*   cn2  = (const int*)d_in[10];
    const int*   pe3  = (const int*)d_in[11];
    const int*   pn3  = (const int*)d_in[12];
    const int*   cn3  = (const int*)d_in[13];
    float* out = (float*)d_out;

    const int n1 = in_sizes[5];    // 600
    const int n3 = in_sizes[11];   // 5400
    const int n_roots = n1 / BR;   // 200

    static cudaStream_t s_side = nullptr;
    static cudaEvent_t  ev_fork = nullptr, ev_join = nullptr;
    if (!s_side) {
        cudaStreamCreateWithFlags(&s_side, cudaStreamNonBlocking);
        cudaEventCreateWithFlags(&ev_fork, cudaEventDisableTiming);
        cudaEventCreateWithFlags(&ev_join, cudaEventDisableTiming);
    }

    // prep + scale resolve only feed gather; run them concurrently with tree_kernel.
    cudaEventRecord(ev_fork, 0);
    cudaStreamWaitEvent(s_side, ev_fork, 0);
    prep_kernel<<<1, 1024, 0, s_side>>>(cn3, n3);
    const int padmax = n3 + 3 * NN;
    scale_fill_kernel<<<(padmax * 16 + 255) / 256, 256, 0, s_side>>>(A, pe3, pn3, cn3);
    cudaEventRecord(ev_join, s_side);

    tree_kernel<<<8 * n_roots, 256>>>(x, A, W, b, root, pn1, cn1, pn2, cn2);

    cudaStreamWaitEvent(0, ev_join, 0);
    gather_kernel<<<8 * NN, 128>>>(x, out);
}